// round 2
// baseline (speedup 1.0000x reference)
#include <cuda_runtime.h>
#include <cuda_bf16.h>
#include <cstdint>

constexpr int Bc = 64, Tc = 256, Ic = 512, Hc = 1024, Oc = 512;

// ------------------------- device scratch (no allocs) -----------------------
__device__ float g_bufA[(size_t)Bc * Tc * Hc];   // xw1 -> out1 (in place)
__device__ float g_bufB[(size_t)Bc * Tc * Hc];   // xw2
__device__ float g_hT[2][Hc * Bc];               // ping-pong hidden, [k][b]
__device__ float g_logits[Bc * Oc];

// grid barrier state (2-level tree), zero-init bss
__device__ unsigned g_grp[16 * 32];
__device__ unsigned g_root;
__device__ unsigned g_gen;

constexpr int RNN_NCTA = 256;

// 2-level grid barrier. Generation counter is monotonic across launches, so
// replays need no reset; each CTA snapshots g_gen at kernel entry.
__device__ __forceinline__ void grid_barrier(unsigned* mygen) {
    __threadfence();                 // release this thread's h-writes
    __syncthreads();
    if (threadIdx.x == 0) {
        const unsigned grp = blockIdx.x & 15u;
        const unsigned grpsz = RNN_NCTA >> 4;
        unsigned a = atomicAdd(&g_grp[grp * 32], 1u);
        if (a == grpsz - 1u) {
            atomicExch(&g_grp[grp * 32], 0u);
            __threadfence();
            unsigned r = atomicAdd(&g_root, 1u);
            if (r == 15u) {
                atomicExch(&g_root, 0u);
                __threadfence();
                atomicAdd(&g_gen, 1u);
            } else {
                while (*(volatile unsigned*)&g_gen == *mygen) __nanosleep(32);
            }
        } else {
            while (*(volatile unsigned*)&g_gen == *mygen) __nanosleep(32);
        }
        __threadfence();             // acquire
    }
    __syncthreads();
    (*mygen)++;
}

// ------------------------- init hidden (transposed) -------------------------
__global__ void init_h_kernel(const float* __restrict__ h0) {
    int idx = blockIdx.x * blockDim.x + threadIdx.x;   // over B*H
    int b = idx >> 10, k = idx & (Hc - 1);
    g_hT[0][k * Bc + b] = h0[idx];
}

// ---- SGEMM (NT): C[M,N] = A[M,K] @ B[N,K]^T + bias0[N] (+ bias1[N]) --------
// 64x64 tile, BK=16, 256 threads, 4x4/thread. M,N mult of 64; K mult of 16.
__global__ void __launch_bounds__(256)
gemm_nt_bias(const float* __restrict__ A, const float* __restrict__ Bm,
             const float* __restrict__ bias0, const float* __restrict__ bias1,
             float* __restrict__ C, int M, int N, int K) {
    __shared__ float sA[16][72];
    __shared__ float sB[16][72];
    const int tid = threadIdx.x;
    const int m0 = blockIdx.y * 64, n0 = blockIdx.x * 64;
    const int lrow = tid >> 2, lkq = tid & 3;
    const float* Ap = A + (size_t)(m0 + lrow) * K + lkq * 4;
    const float* Bp = Bm + (size_t)(n0 + lrow) * K + lkq * 4;
    const int tx = tid & 15, ty = tid >> 4;

    float acc[4][4];
#pragma unroll
    for (int i = 0; i < 4; i++)
#pragma unroll
        for (int j = 0; j < 4; j++) acc[i][j] = 0.f;

    for (int kk = 0; kk < K; kk += 16) {
        float4 a = *reinterpret_cast<const float4*>(Ap + kk);
        float4 b = *reinterpret_cast<const float4*>(Bp + kk);
        __syncthreads();
        sA[lkq * 4 + 0][lrow] = a.x; sA[lkq * 4 + 1][lrow] = a.y;
        sA[lkq * 4 + 2][lrow] = a.z; sA[lkq * 4 + 3][lrow] = a.w;
        sB[lkq * 4 + 0][lrow] = b.x; sB[lkq * 4 + 1][lrow] = b.y;
        sB[lkq * 4 + 2][lrow] = b.z; sB[lkq * 4 + 3][lrow] = b.w;
        __syncthreads();
#pragma unroll
        for (int k = 0; k < 16; k++) {
            float4 av = *reinterpret_cast<const float4*>(&sA[k][ty * 4]);
            float4 bv = *reinterpret_cast<const float4*>(&sB[k][tx * 4]);
            float am[4] = {av.x, av.y, av.z, av.w};
            float bn[4] = {bv.x, bv.y, bv.z, bv.w};
#pragma unroll
            for (int i = 0; i < 4; i++)
#pragma unroll
                for (int j = 0; j < 4; j++)
                    acc[i][j] = fmaf(am[i], bn[j], acc[i][j]);
        }
    }
    float bn[4];
#pragma unroll
    for (int j = 0; j < 4; j++) {
        int n = n0 + tx * 4 + j;
        float bv = bias0 ? bias0[n] : 0.f;
        if (bias1) bv += bias1[n];
        bn[j] = bv;
    }
#pragma unroll
    for (int i = 0; i < 4; i++) {
        int m = m0 + ty * 4 + i;
        float4 o = {acc[i][0] + bn[0], acc[i][1] + bn[1],
                    acc[i][2] + bn[2], acc[i][3] + bn[3]};
        *reinterpret_cast<float4*>(&C[(size_t)m * N + n0 + tx * 4]) = o;
    }
}

// ---- persistent RNN layer: h = tanh(xw[:,t,:] + h @ W_hh^T), t = 0..T-1 ----
// 256 CTAs x 128 thr. CTA tile: 16 b x 16 j. W slice stationary in smem.
constexpr int UR = 16;
constexpr int NKB = Hc / UR;   // 64

template <bool WRITE_OUT>
__global__ void __launch_bounds__(128, 2)
rnn_layer_kernel(const float* __restrict__ W_hh, float* __restrict__ xw) {
    extern __shared__ float Ws[];   // Ws[k*16 + j] = W_hh[j0+j][k], 64KB

    const int tid = threadIdx.x;
    const int jt = blockIdx.x & 63, bt = blockIdx.x >> 6;
    const int j0 = jt * 16, b0 = bt * 16;

#pragma unroll 1
    for (int jj = 0; jj < 16; jj++) {
        const float* wrow = W_hh + (size_t)(j0 + jj) * Hc;
        for (int k = tid; k < Hc; k += 128) Ws[k * 16 + jj] = wrow[k];
    }

    const int j = tid & 15, bq = tid >> 4;
    const int jg = j0 + j;
    const int bl = b0 + bq * 2;

    unsigned mygen = *(volatile unsigned*)&g_gen;
    __syncthreads();

    float* xwp0 = xw + (size_t)bl * Tc * Hc + jg;
    float* xwp1 = xw + (size_t)(bl + 1) * Tc * Hc + jg;

    for (int t = 0; t < Tc; t++) {
        const float* hT = g_hT[t & 1];
        float* hN = g_hT[(t + 1) & 1];
        const float2* __restrict__ hp = reinterpret_cast<const float2*>(hT + bl);

        float2 acc;
        acc.x = xwp0[(size_t)t * Hc];
        acc.y = xwp1[(size_t)t * Hc];

        float2 hA[UR], hB[UR];
        float  wA[UR], wB[UR];
#pragma unroll
        for (int u = 0; u < UR; u++) {
            hA[u] = __ldcg(hp + u * 32);
            wA[u] = Ws[u * 16 + j];
        }
#pragma unroll 1
        for (int kb = 0; kb < NKB; kb += 2) {
            const int k1 = (kb + 1) * UR;
#pragma unroll
            for (int u = 0; u < UR; u++) {
                hB[u] = __ldcg(hp + (k1 + u) * 32);
                wB[u] = Ws[(k1 + u) * 16 + j];
            }
#pragma unroll
            for (int u = 0; u < UR; u++) {
                acc.x = fmaf(wA[u], hA[u].x, acc.x);
                acc.y = fmaf(wA[u], hA[u].y, acc.y);
            }
            if (kb + 2 < NKB) {
                const int k2 = (kb + 2) * UR;
#pragma unroll
                for (int u = 0; u < UR; u++) {
                    hA[u] = __ldcg(hp + (k2 + u) * 32);
                    wA[u] = Ws[(k2 + u) * 16 + j];
                }
            }
#pragma unroll
            for (int u = 0; u < UR; u++) {
                acc.x = fmaf(wB[u], hB[u].x, acc.x);
                acc.y = fmaf(wB[u], hB[u].y, acc.y);
            }
        }

        float2 v = make_float2(tanhf(acc.x), tanhf(acc.y));
        __stcg(reinterpret_cast<float2*>(hN + (size_t)jg * Bc + bl), v);
        if (WRITE_OUT) {
            xwp0[(size_t)t * Hc] = v.x;
            xwp1[(size_t)t * Hc] = v.y;
        }
        grid_barrier(&mygen);
    }
}

// h2 (transposed, in g_hT[0]) -> out[B*O + b*H + k]
__global__ void h2_out_kernel(float* __restrict__ out) {
    int idx = blockIdx.x * blockDim.x + threadIdx.x;   // over B*H
    int b = idx >> 10, k = idx & (Hc - 1);
    out[Bc * Oc + idx] = g_hT[0][k * Bc + b];
}

// softmax over rows of logits[B, O] -> out[0 .. B*O)
__global__ void __launch_bounds__(128)
softmax_kernel(const float* __restrict__ logits, float* __restrict__ out) {
    __shared__ float red[128];
    const int r = blockIdx.x, tid = threadIdx.x;
    const float* row = logits + (size_t)r * Oc;
    float m = -1e30f;
#pragma unroll
    for (int i = 0; i < 4; i++) m = fmaxf(m, row[tid + i * 128]);
    red[tid] = m; __syncthreads();
    for (int s = 64; s > 0; s >>= 1) {
        if (tid < s) red[tid] = fmaxf(red[tid], red[tid + s]);
        __syncthreads();
    }
    m = red[0]; __syncthreads();
    float v[4], sum = 0.f;
#pragma unroll
    for (int i = 0; i < 4; i++) { v[i] = expf(row[tid + i * 128] - m); sum += v[i]; }
    red[tid] = sum; __syncthreads();
    for (int s = 64; s > 0; s >>= 1) {
        if (tid < s) red[tid] += red[tid + s];
        __syncthreads();
    }
    float inv = 1.f / red[0];
#pragma unroll
    for (int i = 0; i < 4; i++) out[(size_t)r * Oc + tid + i * 128] = v[i] * inv;
}

// ----------------------------- launch ---------------------------------------
extern "C" void kernel_launch(void* const* d_in, const int* in_sizes, int n_in,
                              void* d_out, int out_size) {
    const float* x     = (const float*)d_in[0];
    const float* h0    = (const float*)d_in[1];
    const float* W_ih1 = (const float*)d_in[2];
    const float* W_hh1 = (const float*)d_in[3];
    const float* b_ih1 = (const float*)d_in[4];
    const float* b_hh1 = (const float*)d_in[5];
    const float* W_ih2 = (const float*)d_in[6];
    const float* W_hh2 = (const float*)d_in[7];
    const float* b_ih2 = (const float*)d_in[8];
    const float* b_hh2 = (const float*)d_in[9];
    const float* W_fc  = (const float*)d_in[10];
    const float* b_fc  = (const float*)d_in[11];
    float* out = (float*)d_out;

    cudaFuncSetAttribute(rnn_layer_kernel<true>,
                         cudaFuncAttributeMaxDynamicSharedMemorySize, 65536);
    cudaFuncSetAttribute(rnn_layer_kernel<false>,
                         cudaFuncAttributeMaxDynamicSharedMemorySize, 65536);

    void *pA, *pB, *pL;
    cudaGetSymbolAddress(&pA, g_bufA);
    cudaGetSymbolAddress(&pB, g_bufB);
    cudaGetSymbolAddress(&pL, g_logits);
    float* bufA = (float*)pA;
    float* bufB = (float*)pB;
    float* logits = (float*)pL;

    init_h_kernel<<<64, 1024>>>(h0);

    // xw1 = x @ W_ih1^T + b_ih1 + b_hh1   [B*T, H]
    gemm_nt_bias<<<dim3(Hc / 64, (Bc * Tc) / 64), 256>>>(
        x, W_ih1, b_ih1, b_hh1, bufA, Bc * Tc, Hc, Ic);

    // layer 1 recurrence (writes out1 into bufA, final h1 -> g_hT[0])
    rnn_layer_kernel<true><<<RNN_NCTA, 128, 65536>>>(W_hh1, bufA);

    // xw2 = out1 @ W_ih2^T + b_ih2 + b_hh2
    gemm_nt_bias<<<dim3(Hc / 64, (Bc * Tc) / 64), 256>>>(
        bufA, W_ih2, b_ih2, b_hh2, bufB, Bc * Tc, Hc, Hc);

    // layer 2 recurrence (initial hidden = h1, already in g_hT[0]; only final
    // hidden matters since logits use out2[:, -1, :] == h2)
    rnn_layer_kernel<false><<<RNN_NCTA, 128, 65536>>>(W_hh2, bufB);

    // h2 -> out[B*O ..] as [B][H]
    h2_out_kernel<<<64, 1024>>>(out);

    // logits = h2 @ W_fc^T + b_fc   (reads h2 from out buffer)
    gemm_nt_bias<<<dim3(Oc / 64, Bc / 64), 256>>>(
        out + Bc * Oc, W_fc, b_fc, nullptr, logits, Bc, Oc, Hc);

    // probs -> out[0 .. B*O)
    softmax_kernel<<<Bc, 128>>>(logits, out);
}

// round 4
// speedup vs baseline: 2.1423x; 2.1423x over previous
#include <cuda_runtime.h>
#include <cuda_bf16.h>
#include <cstdint>

constexpr int Bc = 64, Tc = 256, Ic = 512, Hc = 1024, Oc = 512;

typedef unsigned long long u64;

// ------------------------- device scratch (no allocs) -----------------------
__device__ float g_bufA[(size_t)Bc * Tc * Hc];   // xw1 -> out1 (in place)
__device__ float g_bufB[(size_t)Bc * Tc * Hc];   // xw2
__device__ float g_h[2][Bc * Hc];                // ping-pong hidden, [b][k]
__device__ float g_logits[Bc * Oc];

// single-level grid barrier state (zero-init bss)
__device__ unsigned g_cnt;
__device__ unsigned g_gen;

constexpr int RNN_NCTA = 128;

// ------------------------- f32x2 helpers ------------------------------------
__device__ __forceinline__ void ffma2(u64& d, u64 a, u64 b) {
    asm("fma.rn.f32x2 %0, %1, %2, %3;" : "=l"(d) : "l"(a), "l"(b), "l"(d));
}
__device__ __forceinline__ float f2sum(u64 v) {
    float lo, hi;
    asm("mov.b64 {%0, %1}, %2;" : "=f"(lo), "=f"(hi) : "l"(v));
    return lo + hi;
}

// ------------------------- grid barrier -------------------------------------
__device__ __forceinline__ void grid_barrier(unsigned* mygen) {
    __syncthreads();
    if (threadIdx.x == 0) {
        __threadfence();   // release h writes
        unsigned a = atomicAdd(&g_cnt, 1u);
        if (a == RNN_NCTA - 1u) {
            atomicExch(&g_cnt, 0u);
            __threadfence();
            atomicAdd(&g_gen, 1u);
        } else {
            volatile unsigned* p = &g_gen;
            while (*p == *mygen) { }
        }
        __threadfence();   // acquire
    }
    __syncthreads();
    (*mygen)++;
}

// ------------------------- init hidden --------------------------------------
__global__ void init_h_kernel(const float* __restrict__ h0) {
    int idx = blockIdx.x * blockDim.x + threadIdx.x;   // over B*H, [b][k]
    g_h[0][idx] = h0[idx];
}

// ---- SGEMM (NT): C[M,N] = A[M,K] @ B[N,K]^T + bias0[N] (+ bias1[N]) --------
// 128x128 tile, BK=16, 256 threads, 8x8/thread, double-buffered smem.
// N must be a multiple of 128; K multiple of 16; M guarded.
constexpr int BM = 128, BN = 128, BKg = 16;

__global__ void __launch_bounds__(256)
gemm_nt_bias(const float* __restrict__ A, const float* __restrict__ Bm,
             const float* __restrict__ bias0, const float* __restrict__ bias1,
             float* __restrict__ C, int M, int N, int K) {
    __shared__ float sA[2][BKg][BM + 4];
    __shared__ float sB[2][BKg][BN + 4];

    const int tid = threadIdx.x;
    const int m0 = blockIdx.y * BM, n0 = blockIdx.x * BN;
    const int lr = tid >> 2;          // 0..63 (two passes cover 128 rows)
    const int lk = (tid & 3) * 4;     // k offset within BK: 0,4,8,12
    const int tx = tid & 15, ty = tid >> 4;

    float4 ra[2], rb[2];
    float acc[8][8];
#pragma unroll
    for (int i = 0; i < 8; i++)
#pragma unroll
        for (int j = 0; j < 8; j++) acc[i][j] = 0.f;

    const int nt = K / BKg;
    const float4 z4 = {0.f, 0.f, 0.f, 0.f};

    // prologue: load tile 0
#pragma unroll
    for (int r = 0; r < 2; r++) {
        int m = m0 + lr + r * 64;
        ra[r] = (m < M) ? *reinterpret_cast<const float4*>(A + (size_t)m * K + lk) : z4;
        int n = n0 + lr + r * 64;
        rb[r] = *reinterpret_cast<const float4*>(Bm + (size_t)n * K + lk);
    }
#pragma unroll
    for (int r = 0; r < 2; r++) {
        sA[0][lk + 0][lr + r * 64] = ra[r].x;
        sA[0][lk + 1][lr + r * 64] = ra[r].y;
        sA[0][lk + 2][lr + r * 64] = ra[r].z;
        sA[0][lk + 3][lr + r * 64] = ra[r].w;
        sB[0][lk + 0][lr + r * 64] = rb[r].x;
        sB[0][lk + 1][lr + r * 64] = rb[r].y;
        sB[0][lk + 2][lr + r * 64] = rb[r].z;
        sB[0][lk + 3][lr + r * 64] = rb[r].w;
    }
    __syncthreads();

    for (int kt = 0; kt < nt; kt++) {
        const int cur = kt & 1;
        if (kt + 1 < nt) {
            const int ko = (kt + 1) * BKg + lk;
#pragma unroll
            for (int r = 0; r < 2; r++) {
                int m = m0 + lr + r * 64;
                ra[r] = (m < M) ? *reinterpret_cast<const float4*>(A + (size_t)m * K + ko) : z4;
                int n = n0 + lr + r * 64;
                rb[r] = *reinterpret_cast<const float4*>(Bm + (size_t)n * K + ko);
            }
        }
#pragma unroll
        for (int k = 0; k < BKg; k++) {
            float av[8], bv[8];
            *reinterpret_cast<float4*>(&av[0]) =
                *reinterpret_cast<const float4*>(&sA[cur][k][ty * 8]);
            *reinterpret_cast<float4*>(&av[4]) =
                *reinterpret_cast<const float4*>(&sA[cur][k][ty * 8 + 4]);
            *reinterpret_cast<float4*>(&bv[0]) =
                *reinterpret_cast<const float4*>(&sB[cur][k][tx * 8]);
            *reinterpret_cast<float4*>(&bv[4]) =
                *reinterpret_cast<const float4*>(&sB[cur][k][tx * 8 + 4]);
#pragma unroll
            for (int i = 0; i < 8; i++)
#pragma unroll
                for (int j = 0; j < 8; j++)
                    acc[i][j] = fmaf(av[i], bv[j], acc[i][j]);
        }
        if (kt + 1 < nt) {
            const int nxt = cur ^ 1;
#pragma unroll
            for (int r = 0; r < 2; r++) {
                sA[nxt][lk + 0][lr + r * 64] = ra[r].x;
                sA[nxt][lk + 1][lr + r * 64] = ra[r].y;
                sA[nxt][lk + 2][lr + r * 64] = ra[r].z;
                sA[nxt][lk + 3][lr + r * 64] = ra[r].w;
                sB[nxt][lk + 0][lr + r * 64] = rb[r].x;
                sB[nxt][lk + 1][lr + r * 64] = rb[r].y;
                sB[nxt][lk + 2][lr + r * 64] = rb[r].z;
                sB[nxt][lk + 3][lr + r * 64] = rb[r].w;
            }
            __syncthreads();
        }
    }

    float bn[8];
#pragma unroll
    for (int j = 0; j < 8; j++) {
        int n = n0 + tx * 8 + j;
        float bv = bias0 ? bias0[n] : 0.f;
        if (bias1) bv += bias1[n];
        bn[j] = bv;
    }
#pragma unroll
    for (int i = 0; i < 8; i++) {
        int m = m0 + ty * 8 + i;
        if (m < M) {
            float4 o0 = {acc[i][0] + bn[0], acc[i][1] + bn[1],
                         acc[i][2] + bn[2], acc[i][3] + bn[3]};
            float4 o1 = {acc[i][4] + bn[4], acc[i][5] + bn[5],
                         acc[i][6] + bn[6], acc[i][7] + bn[7]};
            *reinterpret_cast<float4*>(&C[(size_t)m * N + n0 + tx * 8])     = o0;
            *reinterpret_cast<float4*>(&C[(size_t)m * N + n0 + tx * 8 + 4]) = o1;
        }
    }
}

// ---- persistent RNN layer: h = tanh(xw[:,t,:] + h @ W_hh^T) -----------------
// 128 CTAs x 128 thr, 1 CTA/SM. CTA tile: 32 j x 16 b. Thread: 1 j x 4 b.
// W slice (32j x 1024k) stationary in smem; h slice (16b x 1024k) staged
// into smem every step (flat 64KB copy, __ldcg for L2 coherence).
constexpr int WS_STRIDE = 1028;   // 1024 + 4 pad
constexpr int RNN_SMEM = (32 * WS_STRIDE + 16 * 1024) * 4;  // 197120 B

template <bool WRITE_OUT>
__global__ void __launch_bounds__(128, 1)
rnn_layer_kernel(const float* __restrict__ W_hh, float* __restrict__ xw) {
    extern __shared__ float sm[];
    float* Wsm = sm;                   // [32][WS_STRIDE]
    float* hsm = sm + 32 * WS_STRIDE;  // [16][1024], flat = global slice

    const int tid = threadIdx.x;
    const int jt = blockIdx.x & 31, bt = blockIdx.x >> 5;  // 32 jt x 4 bt
    const int j0 = jt * 32, b0 = bt * 16;

    // one-time W slice load (coalesced float4)
    for (int idx = tid; idx < 32 * 256; idx += 128) {
        int jj = idx >> 8, k4 = idx & 255;
        float4 w = *reinterpret_cast<const float4*>(
            W_hh + (size_t)(j0 + jj) * Hc + k4 * 4);
        *reinterpret_cast<float4*>(&Wsm[jj * WS_STRIDE + k4 * 4]) = w;
    }

    const int j = tid & 31, bq = tid >> 5;   // warp = 32 j, same bq
    const int jg = j0 + j;
    const int bl = b0 + bq * 4;              // 4 batches per thread

    unsigned mygen = *(volatile unsigned*)&g_gen;
    __syncthreads();

    const float* wrow = Wsm + j * WS_STRIDE;
    const float* hrow = hsm + bq * 4 * 1024;

    float* xwp[4];
#pragma unroll
    for (int b = 0; b < 4; b++)
        xwp[b] = xw + (size_t)(bl + b) * Tc * Hc + jg;

    for (int t = 0; t < Tc; t++) {
        // prefetch xw for this step (independent of h)
        float xwv[4];
#pragma unroll
        for (int b = 0; b < 4; b++) xwv[b] = __ldg(xwp[b] + (size_t)t * Hc);

        // stage h slice: flat 64KB copy, 32 float4 per thread
        {
            const float4* src = reinterpret_cast<const float4*>(
                g_h[t & 1] + (size_t)b0 * Hc);
            float4* dst = reinterpret_cast<float4*>(hsm);
#pragma unroll
            for (int u = 0; u < 32; u++) {
                int idx = u * 128 + tid;
                dst[idx] = __ldcg(src + idx);
            }
        }
        __syncthreads();

        u64 accA[4] = {0ull, 0ull, 0ull, 0ull};
        u64 accB[4] = {0ull, 0ull, 0ull, 0ull};
#pragma unroll 8
        for (int kq = 0; kq < 256; kq++) {
            ulonglong2 w2 = *reinterpret_cast<const ulonglong2*>(wrow + kq * 4);
#pragma unroll
            for (int b = 0; b < 4; b++) {
                ulonglong2 hv = *reinterpret_cast<const ulonglong2*>(
                    hrow + b * 1024 + kq * 4);
                ffma2(accA[b], w2.x, hv.x);
                ffma2(accB[b], w2.y, hv.y);
            }
        }

        float* hn = g_h[(t + 1) & 1];
#pragma unroll
        for (int b = 0; b < 4; b++) {
            float v = tanhf(xwv[b] + f2sum(accA[b]) + f2sum(accB[b]));
            __stcg(hn + (size_t)(bl + b) * Hc + jg, v);
            if (WRITE_OUT) xwp[b][(size_t)t * Hc] = v;
        }
        grid_barrier(&mygen);
    }
}

// h2 ([b][k] in g_h[0]) -> out[B*O + idx]
__global__ void h2_out_kernel(float* __restrict__ out) {
    int idx = blockIdx.x * blockDim.x + threadIdx.x;
    out[Bc * Oc + idx] = g_h[0][idx];
}

// softmax over rows of logits[B, O] -> out[0 .. B*O)
__global__ void __launch_bounds__(128)
softmax_kernel(const float* __restrict__ logits, float* __restrict__ out) {
    __shared__ float red[128];
    const int r = blockIdx.x, tid = threadIdx.x;
    const float* row = logits + (size_t)r * Oc;
    float m = -1e30f;
#pragma unroll
    for (int i = 0; i < 4; i++) m = fmaxf(m, row[tid + i * 128]);
    red[tid] = m; __syncthreads();
    for (int s = 64; s > 0; s >>= 1) {
        if (tid < s) red[tid] = fmaxf(red[tid], red[tid + s]);
        __syncthreads();
    }
    m = red[0]; __syncthreads();
    float v[4], sum = 0.f;
#pragma unroll
    for (int i = 0; i < 4; i++) { v[i] = expf(row[tid + i * 128] - m); sum += v[i]; }
    red[tid] = sum; __syncthreads();
    for (int s = 64; s > 0; s >>= 1) {
        if (tid < s) red[tid] += red[tid + s];
        __syncthreads();
    }
    float inv = 1.f / red[0];
#pragma unroll
    for (int i = 0; i < 4; i++) out[(size_t)r * Oc + tid + i * 128] = v[i] * inv;
}

// ----------------------------- launch ---------------------------------------
extern "C" void kernel_launch(void* const* d_in, const int* in_sizes, int n_in,
                              void* d_out, int out_size) {
    const float* x     = (const float*)d_in[0];
    const float* h0    = (const float*)d_in[1];
    const float* W_ih1 = (const float*)d_in[2];
    const float* W_hh1 = (const float*)d_in[3];
    const float* b_ih1 = (const float*)d_in[4];
    const float* b_hh1 = (const float*)d_in[5];
    const float* W_ih2 = (const float*)d_in[6];
    const float* W_hh2 = (const float*)d_in[7];
    const float* b_ih2 = (const float*)d_in[8];
    const float* b_hh2 = (const float*)d_in[9];
    const float* W_fc  = (const float*)d_in[10];
    const float* b_fc  = (const float*)d_in[11];
    float* out = (float*)d_out;

    cudaFuncSetAttribute(rnn_layer_kernel<true>,
                         cudaFuncAttributeMaxDynamicSharedMemorySize, RNN_SMEM);
    cudaFuncSetAttribute(rnn_layer_kernel<false>,
                         cudaFuncAttributeMaxDynamicSharedMemorySize, RNN_SMEM);

    void *pA, *pB, *pL;
    cudaGetSymbolAddress(&pA, g_bufA);
    cudaGetSymbolAddress(&pB, g_bufB);
    cudaGetSymbolAddress(&pL, g_logits);
    float* bufA = (float*)pA;
    float* bufB = (float*)pB;
    float* logits = (float*)pL;

    init_h_kernel<<<64, 1024>>>(h0);

    // xw1 = x @ W_ih1^T + b_ih1 + b_hh1   [B*T, H]
    gemm_nt_bias<<<dim3(Hc / BN, (Bc * Tc) / BM), 256>>>(
        x, W_ih1, b_ih1, b_hh1, bufA, Bc * Tc, Hc, Ic);

    // layer 1 recurrence (writes out1 into bufA, final h1 -> g_h[0])
    rnn_layer_kernel<true><<<RNN_NCTA, 128, RNN_SMEM>>>(W_hh1, bufA);

    // xw2 = out1 @ W_ih2^T + b_ih2 + b_hh2
    gemm_nt_bias<<<dim3(Hc / BN, (Bc * Tc) / BM), 256>>>(
        bufA, W_ih2, b_ih2, b_hh2, bufB, Bc * Tc, Hc, Hc);

    // layer 2 recurrence (initial hidden = h1, already in g_h[0])
    rnn_layer_kernel<false><<<RNN_NCTA, 128, RNN_SMEM>>>(W_hh2, bufB);

    // h2 -> out[B*O ..] as [b][k]
    h2_out_kernel<<<64, 1024>>>(out);

    // logits = h2 @ W_fc^T + b_fc  (M=64 handled by guards)
    gemm_nt_bias<<<dim3(Oc / BN, 1), 256>>>(
        out + Bc * Oc, W_fc, b_fc, nullptr, logits, Bc, Oc, Hc);

    // probs -> out[0 .. B*O)
    softmax_kernel<<<Bc, 128>>>(logits, out);
}

// round 6
// speedup vs baseline: 2.2671x; 1.0583x over previous
#include <cuda_runtime.h>
#include <cuda_bf16.h>
#include <cstdint>

constexpr int Bc = 64, Tc = 256, Ic = 512, Hc = 1024, Oc = 512;

typedef unsigned long long u64;

// ------------------------- device scratch (no allocs) -----------------------
__device__ float g_bufA[(size_t)Bc * Tc * Hc];   // xw1 -> out1 (in place)
__device__ float g_bufB[(size_t)Bc * Tc * Hc];   // xw2
__device__ float g_h[2][Bc * Hc];                // ping-pong hidden, [b][k]
__device__ float g_logits[Bc * Oc];

// per-bt-group barrier state (zero-init bss), line-separated
__device__ unsigned g_cnt4[4 * 32];
__device__ unsigned g_gen4[4 * 32];

// ------------------------- helpers ------------------------------------------
__device__ __forceinline__ void ffma2(u64& d, u64 a, u64 b) {
    asm("fma.rn.f32x2 %0, %1, %2, %3;" : "=l"(d) : "l"(a), "l"(b), "l"(d));
}
__device__ __forceinline__ float f2sum(u64 v) {
    float lo, hi;
    asm("mov.b64 {%0, %1}, %2;" : "=f"(lo), "=f"(hi) : "l"(v));
    return lo + hi;
}
__device__ __forceinline__ void cp16(uint32_t s, const void* g) {
    asm volatile("cp.async.cg.shared.global [%0], [%1], 16;" :: "r"(s), "l"(g));
}
__device__ __forceinline__ void cp_commit() {
    asm volatile("cp.async.commit_group;");
}
__device__ __forceinline__ void cp_wait0() {
    asm volatile("cp.async.wait_group 0;");
}

// 32-CTA group barrier (group = bt). Generation counters are monotonic across
// launches; each CTA snapshots its group counter at kernel entry.
__device__ __forceinline__ void group_barrier(unsigned* mygen, int bt) {
    __syncthreads();
    if (threadIdx.x == 0) {
        __threadfence();   // release h writes
        unsigned a = atomicAdd(&g_cnt4[bt * 32], 1u);
        if (a == 31u) {
            atomicExch(&g_cnt4[bt * 32], 0u);
            __threadfence();
            atomicAdd(&g_gen4[bt * 32], 1u);
        } else {
            volatile unsigned* p = &g_gen4[bt * 32];
            while (*p == *mygen) { }
        }
        __threadfence();   // acquire
    }
    __syncthreads();
    (*mygen)++;
}

// ------------------------- init hidden --------------------------------------
__global__ void init_h_kernel(const float* __restrict__ h0) {
    int idx = blockIdx.x * blockDim.x + threadIdx.x;   // over B*H, [b][k]
    g_h[0][idx] = h0[idx];
}

// ---- SGEMM (NT): C[M,N] = A[M,K] @ B[N,K]^T + bias0[N] (+ bias1[N]) --------
// 128x128 tile, BK=16, 256 threads, 8x8/thread, double-buffered smem.
// N multiple of 128; K multiple of 16; M guarded.
constexpr int BM = 128, BN = 128, BKg = 16;

__global__ void __launch_bounds__(256, 2)
gemm_nt_bias(const float* __restrict__ A, const float* __restrict__ Bm,
             const float* __restrict__ bias0, const float* __restrict__ bias1,
             float* __restrict__ C, int M, int N, int K) {
    __shared__ float sA[2][BKg][BM + 4];
    __shared__ float sB[2][BKg][BN + 4];

    const int tid = threadIdx.x;
    const int m0 = blockIdx.y * BM, n0 = blockIdx.x * BN;
    const int lr = tid >> 2;
    const int lk = (tid & 3) * 4;
    const int tx = tid & 15, ty = tid >> 4;

    float4 ra[2], rb[2];
    float acc[8][8];
#pragma unroll
    for (int i = 0; i < 8; i++)
#pragma unroll
        for (int j = 0; j < 8; j++) acc[i][j] = 0.f;

    const int nt = K / BKg;
    const float4 z4 = {0.f, 0.f, 0.f, 0.f};

#pragma unroll
    for (int r = 0; r < 2; r++) {
        int m = m0 + lr + r * 64;
        ra[r] = (m < M) ? *reinterpret_cast<const float4*>(A + (size_t)m * K + lk) : z4;
        int n = n0 + lr + r * 64;
        rb[r] = *reinterpret_cast<const float4*>(Bm + (size_t)n * K + lk);
    }
#pragma unroll
    for (int r = 0; r < 2; r++) {
        sA[0][lk + 0][lr + r * 64] = ra[r].x;
        sA[0][lk + 1][lr + r * 64] = ra[r].y;
        sA[0][lk + 2][lr + r * 64] = ra[r].z;
        sA[0][lk + 3][lr + r * 64] = ra[r].w;
        sB[0][lk + 0][lr + r * 64] = rb[r].x;
        sB[0][lk + 1][lr + r * 64] = rb[r].y;
        sB[0][lk + 2][lr + r * 64] = rb[r].z;
        sB[0][lk + 3][lr + r * 64] = rb[r].w;
    }
    __syncthreads();

    for (int kt = 0; kt < nt; kt++) {
        const int cur = kt & 1;
        if (kt + 1 < nt) {
            const int ko = (kt + 1) * BKg + lk;
#pragma unroll
            for (int r = 0; r < 2; r++) {
                int m = m0 + lr + r * 64;
                ra[r] = (m < M) ? *reinterpret_cast<const float4*>(A + (size_t)m * K + ko) : z4;
                int n = n0 + lr + r * 64;
                rb[r] = *reinterpret_cast<const float4*>(Bm + (size_t)n * K + ko);
            }
        }
#pragma unroll
        for (int k = 0; k < BKg; k++) {
            float av[8], bv[8];
            *reinterpret_cast<float4*>(&av[0]) =
                *reinterpret_cast<const float4*>(&sA[cur][k][ty * 8]);
            *reinterpret_cast<float4*>(&av[4]) =
                *reinterpret_cast<const float4*>(&sA[cur][k][ty * 8 + 4]);
            *reinterpret_cast<float4*>(&bv[0]) =
                *reinterpret_cast<const float4*>(&sB[cur][k][tx * 8]);
            *reinterpret_cast<float4*>(&bv[4]) =
                *reinterpret_cast<const float4*>(&sB[cur][k][tx * 8 + 4]);
#pragma unroll
            for (int i = 0; i < 8; i++)
#pragma unroll
                for (int j = 0; j < 8; j++)
                    acc[i][j] = fmaf(av[i], bv[j], acc[i][j]);
        }
        if (kt + 1 < nt) {
            const int nxt = cur ^ 1;
#pragma unroll
            for (int r = 0; r < 2; r++) {
                sA[nxt][lk + 0][lr + r * 64] = ra[r].x;
                sA[nxt][lk + 1][lr + r * 64] = ra[r].y;
                sA[nxt][lk + 2][lr + r * 64] = ra[r].z;
                sA[nxt][lk + 3][lr + r * 64] = ra[r].w;
                sB[nxt][lk + 0][lr + r * 64] = rb[r].x;
                sB[nxt][lk + 1][lr + r * 64] = rb[r].y;
                sB[nxt][lk + 2][lr + r * 64] = rb[r].z;
                sB[nxt][lk + 3][lr + r * 64] = rb[r].w;
            }
            __syncthreads();
        }
    }

    float bn[8];
#pragma unroll
    for (int j = 0; j < 8; j++) {
        int n = n0 + tx * 8 + j;
        float bv = bias0 ? bias0[n] : 0.f;
        if (bias1) bv += bias1[n];
        bn[j] = bv;
    }
#pragma unroll
    for (int i = 0; i < 8; i++) {
        int m = m0 + ty * 8 + i;
        if (m < M) {
            float4 o0 = {acc[i][0] + bn[0], acc[i][1] + bn[1],
                         acc[i][2] + bn[2], acc[i][3] + bn[3]};
            float4 o1 = {acc[i][4] + bn[4], acc[i][5] + bn[5],
                         acc[i][6] + bn[6], acc[i][7] + bn[7]};
            *reinterpret_cast<float4*>(&C[(size_t)m * N + n0 + tx * 8])     = o0;
            *reinterpret_cast<float4*>(&C[(size_t)m * N + n0 + tx * 8 + 4]) = o1;
        }
    }
}

// ---- persistent RNN layer: h = tanh(xw[:,t,:] + h @ W_hh^T) -----------------
// 128 CTAs x 256 thr, 1 CTA/SM. CTA tile: 32 j x 16 b. Warp (ks, wlo):
//   lane = j (0..31), wlo -> 4 batches, ks -> k-half. Thread: 1 j x 4 b x 512 k.
// W slice (32j x 1024k) stationary in smem. Each warp cp.async-stages exactly
// the 8KB h block it consumes (no block sync for staging). k-halves combined
// through a small smem buffer; barrier is per-bt-group (32 CTAs).
constexpr int WS_STRIDE = 1028;   // floats; 1028*4 B = 16-aligned, conflict-min
constexpr int HSM_OFF = 32 * WS_STRIDE;           // floats
constexpr int RED_OFF = HSM_OFF + 16 * 1024;      // floats
constexpr int RNN_SMEM = (RED_OFF + 512) * 4;     // bytes

template <bool WRITE_OUT>
__global__ void __launch_bounds__(256, 1)
rnn_layer_kernel(const float* __restrict__ W_hh, float* __restrict__ xw) {
    extern __shared__ float sm[];
    float* Wsm = sm;
    float* hsm = sm + HSM_OFF;
    float* redsm = sm + RED_OFF;

    const int tid = threadIdx.x;
    const int jt = blockIdx.x & 31, bt = blockIdx.x >> 5;
    const int j0 = jt * 32, b0 = bt * 16;

    // one-time W slice load
    for (int idx = tid; idx < 32 * 256; idx += 256) {
        int jj = idx >> 8, k4 = idx & 255;
        float4 w = *reinterpret_cast<const float4*>(
            W_hh + (size_t)(j0 + jj) * Hc + k4 * 4);
        *reinterpret_cast<float4*>(&Wsm[jj * WS_STRIDE + k4 * 4]) = w;
    }

    const int lane = tid & 31;          // j index
    const int warp = tid >> 5;          // 0..7
    const int ks = warp >> 2;           // k-half
    const int wlo = warp & 3;           // batch quad
    const int jg = j0 + lane;
    const int bl = b0 + wlo * 4;

    unsigned mygen;
    {
        volatile unsigned* p = &g_gen4[bt * 32];
        mygen = *p;
    }
    __syncthreads();

    const float* wp = Wsm + lane * WS_STRIDE + ks * 512;
    const float* hp = hsm + wlo * 4 * 1024 + ks * 512;
    const uint32_t hsm_s = (uint32_t)__cvta_generic_to_shared(hsm);

    float* xwp[4];
#pragma unroll
    for (int b = 0; b < 4; b++)
        xwp[b] = xw + (size_t)(bl + b) * Tc * Hc + jg;

    // prologue xw prefetch (only ks==0 consumes xw)
    float xwv[4];
    if (ks == 0) {
#pragma unroll
        for (int b = 0; b < 4; b++) xwv[b] = __ldg(xwp[b]);
    }

    for (int t = 0; t < Tc; t++) {
        // stage this warp's 8KB h block: rows [bl..bl+4) x k-half
        {
            const float* hg = g_h[t & 1] + (size_t)b0 * Hc;
#pragma unroll
            for (int r = 0; r < 4; r++)
#pragma unroll
                for (int c = 0; c < 4; c++) {
                    int off = (wlo * 4 + r) * 1024 + ks * 512 + (c * 32 + lane) * 4;
                    cp16(hsm_s + off * 4, hg + off);
                }
            cp_commit();
            cp_wait0();
            __syncwarp();
        }

        u64 accA[4] = {0ull, 0ull, 0ull, 0ull};
        u64 accB[4] = {0ull, 0ull, 0ull, 0ull};
#pragma unroll 8
        for (int kq = 0; kq < 128; kq++) {
            ulonglong2 w2 = *reinterpret_cast<const ulonglong2*>(wp + kq * 4);
#pragma unroll
            for (int b = 0; b < 4; b++) {
                ulonglong2 hv = *reinterpret_cast<const ulonglong2*>(
                    hp + b * 1024 + kq * 4);
                ffma2(accA[b], w2.x, hv.x);
                ffma2(accB[b], w2.y, hv.y);
            }
        }

        float part[4];
#pragma unroll
        for (int b = 0; b < 4; b++) part[b] = f2sum(accA[b]) + f2sum(accB[b]);

        if (ks == 1) {
#pragma unroll
            for (int b = 0; b < 4; b++)
                redsm[wlo * 128 + b * 32 + lane] = part[b];
        }
        __syncthreads();

        if (ks == 0) {
            float* hn = g_h[(t + 1) & 1];
#pragma unroll
            for (int b = 0; b < 4; b++) {
                float tot = part[b] + redsm[wlo * 128 + b * 32 + lane];
                float v = tanhf(xwv[b] + tot);
                __stcg(hn + (size_t)(bl + b) * Hc + jg, v);
                if (WRITE_OUT) xwp[b][(size_t)t * Hc] = v;
            }
            // prefetch next step's xw (hidden behind the barrier wait)
            if (t + 1 < Tc) {
#pragma unroll
                for (int b = 0; b < 4; b++)
                    xwv[b] = __ldg(xwp[b] + (size_t)(t + 1) * Hc);
            }
        }

        group_barrier(&mygen, bt);
    }
}

// h2 ([b][k] in g_h[0]) -> out[B*O + idx]
__global__ void h2_out_kernel(float* __restrict__ out) {
    int idx = blockIdx.x * blockDim.x + threadIdx.x;
    out[Bc * Oc + idx] = g_h[0][idx];
}

// softmax over rows of logits[B, O] -> out[0 .. B*O)
__global__ void __launch_bounds__(128)
softmax_kernel(const float* __restrict__ logits, float* __restrict__ out) {
    __shared__ float red[128];
    const int r = blockIdx.x, tid = threadIdx.x;
    const float* row = logits + (size_t)r * Oc;
    float m = -1e30f;
#pragma unroll
    for (int i = 0; i < 4; i++) m = fmaxf(m, row[tid + i * 128]);
    red[tid] = m; __syncthreads();
    for (int s = 64; s > 0; s >>= 1) {
        if (tid < s) red[tid] = fmaxf(red[tid], red[tid + s]);
        __syncthreads();
    }
    m = red[0]; __syncthreads();
    float v[4], sum = 0.f;
#pragma unroll
    for (int i = 0; i < 4; i++) { v[i] = expf(row[tid + i * 128] - m); sum += v[i]; }
    red[tid] = sum; __syncthreads();
    for (int s = 64; s > 0; s >>= 1) {
        if (tid < s) red[tid] += red[tid + s];
        __syncthreads();
    }
    float inv = 1.f / red[0];
#pragma unroll
    for (int i = 0; i < 4; i++) out[(size_t)r * Oc + tid + i * 128] = v[i] * inv;
}

// ----------------------------- launch ---------------------------------------
extern "C" void kernel_launch(void* const* d_in, const int* in_sizes, int n_in,
                              void* d_out, int out_size) {
    const float* x     = (const float*)d_in[0];
    const float* h0    = (const float*)d_in[1];
    const float* W_ih1 = (const float*)d_in[2];
    const float* W_hh1 = (const float*)d_in[3];
    const float* b_ih1 = (const float*)d_in[4];
    const float* b_hh1 = (const float*)d_in[5];
    const float* W_ih2 = (const float*)d_in[6];
    const float* W_hh2 = (const float*)d_in[7];
    const float* b_ih2 = (const float*)d_in[8];
    const float* b_hh2 = (const float*)d_in[9];
    const float* W_fc  = (const float*)d_in[10];
    const float* b_fc  = (const float*)d_in[11];
    float* out = (float*)d_out;

    cudaFuncSetAttribute(rnn_layer_kernel<true>,
                         cudaFuncAttributeMaxDynamicSharedMemorySize, RNN_SMEM);
    cudaFuncSetAttribute(rnn_layer_kernel<false>,
                         cudaFuncAttributeMaxDynamicSharedMemorySize, RNN_SMEM);

    void *pA, *pB, *pL;
    cudaGetSymbolAddress(&pA, g_bufA);
    cudaGetSymbolAddress(&pB, g_bufB);
    cudaGetSymbolAddress(&pL, g_logits);
    float* bufA = (float*)pA;
    float* bufB = (float*)pB;
    float* logits = (float*)pL;

    init_h_kernel<<<64, 1024>>>(h0);

    // xw1 = x @ W_ih1^T + b_ih1 + b_hh1   [B*T, H]
    gemm_nt_bias<<<dim3(Hc / BN, (Bc * Tc) / BM), 256>>>(
        x, W_ih1, b_ih1, b_hh1, bufA, Bc * Tc, Hc, Ic);

    // layer 1 recurrence (writes out1 into bufA, final h1 -> g_h[0])
    rnn_layer_kernel<true><<<128, 256, RNN_SMEM>>>(W_hh1, bufA);

    // xw2 = out1 @ W_ih2^T + b_ih2 + b_hh2
    gemm_nt_bias<<<dim3(Hc / BN, (Bc * Tc) / BM), 256>>>(
        bufA, W_ih2, b_ih2, b_hh2, bufB, Bc * Tc, Hc, Hc);

    // layer 2 recurrence (initial hidden = h1, already in g_h[0])
    rnn_layer_kernel<false><<<128, 256, RNN_SMEM>>>(W_hh2, bufB);

    // h2 -> out[B*O ..] as [b][k]
    h2_out_kernel<<<64, 1024>>>(out);

    // logits = h2 @ W_fc^T + b_fc  (M=64 handled by guards)
    gemm_nt_bias<<<dim3(Oc / BN, 1), 256>>>(
        out + Bc * Oc, W_fc, b_fc, nullptr, logits, Bc, Oc, Hc);

    // probs -> out[0 .. B*O)
    softmax_kernel<<<Bc, 128>>>(logits, out);
}